// round 6
// baseline (speedup 1.0000x reference)
#include <cuda_runtime.h>
#include <cuda_fp16.h>
#include <cstdint>
#include <math.h>

#define Hh 4
#define Tt 1024
#define Dd 8192
#define SCALE 0.011048543456039806f  /* 1/sqrt(8192) */

// ---------------- scratch (static device arrays; no allocation) -------------
__device__ __half g_qh[(size_t)Hh * Tt * Dd];   // 64 MB  rope'd query fp16
__device__ __half g_vt[(size_t)Hh * Dd * Tt];   // 64 MB  V^T [h][d][s] fp16
__device__ __half g_sh[(size_t)Hh * Tt * Tt];   // 8 MB   masked scores fp16

// ---------------- helpers (base-arch PTX only: cp.async/ldmatrix/mma.sync) --
__device__ __forceinline__ uint32_t smem_u32(const void* p) {
    uint32_t a;
    asm("{ .reg .u64 t; cvta.to.shared.u64 t, %1; cvt.u32.u64 %0, t; }" : "=r"(a) : "l"(p));
    return a;
}
__device__ __forceinline__ void cp16(uint32_t dst, const void* src) {
    asm volatile("cp.async.cg.shared.global [%0], [%1], 16;" :: "r"(dst), "l"(src) : "memory");
}
#define CP_COMMIT asm volatile("cp.async.commit_group;" ::: "memory")
#define CP_WAIT2  asm volatile("cp.async.wait_group 2;" ::: "memory")

__device__ __forceinline__ void ldsm4(uint32_t& r0, uint32_t& r1, uint32_t& r2, uint32_t& r3,
                                      uint32_t a) {
    asm volatile("ldmatrix.sync.aligned.m8n8.x4.shared.b16 {%0,%1,%2,%3}, [%4];"
                 : "=r"(r0), "=r"(r1), "=r"(r2), "=r"(r3) : "r"(a));
}
__device__ __forceinline__ void mma16816(float* c,
                                         uint32_t a0, uint32_t a1, uint32_t a2, uint32_t a3,
                                         uint32_t b0, uint32_t b1) {
    asm volatile(
        "mma.sync.aligned.m16n8k16.row.col.f32.f16.f16.f32 "
        "{%0,%1,%2,%3},{%4,%5,%6,%7},{%8,%9},{%0,%1,%2,%3};"
        : "+f"(c[0]), "+f"(c[1]), "+f"(c[2]), "+f"(c[3])
        : "r"(a0), "r"(a1), "r"(a2), "r"(a3), "r"(b0), "r"(b1));
}

// 128B rows (64 halves of K per sub-tile), XOR swizzle: conflict-free
#define SWZ(row, cb) ((row) * 128 + ((cb) ^ (((row) & 7) << 4)))

// BK = 128: each operand tile = 2 sub-tiles of [128 rows x 128B] = 32 KB
#define SUB_BYTES   16384
#define OPER_BYTES  32768
#define STAGE_BYTES 65536   /* A | B */
#define NSTAGE      3

// ---------------------------------------------------------------------------
// Kernel 1: bug-faithful ROPE -> fp16
// ---------------------------------------------------------------------------
__global__ void rope_kernel(const float* __restrict__ q) {
    long idx = (long)blockIdx.x * 256 + threadIdx.x;   // pair index
    int m   = (int)(idx & (Dd / 2 - 1));
    int row = (int)(idx >> 12);
    int t = row & (Tt - 1);
    int h = row >> 10;

    const float* qrow = q + ((long)row << 13);
    float v0 = qrow[2 * m];
    float v1 = qrow[2 * m + 1];

    int q2   = t & 1;
    int dsrc = (q2 << 12) + m;
    int tsrc = ((h & 1) << 9) + (t >> 1);
    int h2   = h >> 1;
    const float* base = q + ((long)(2 * h2) << 23);
    float rot0 = -base[(1L << 23) + (long)tsrc * Dd + dsrc];
    float rot1 =  base[(long)tsrc * Dd + dsrc];

    float freq = exp2f(-(float)m * (1.0f / 256.0f)) * 0.15915494309189535f;
    float ph = fmodf((float)t * freq, 1.0f);
    float c = cospif(2.0f * ph);
    float s = sinpif(2.0f * ph);

    float o0 = v0 * c + rot0 * s;
    float o1 = v1 * c + rot1 * s;

    long off = ((long)row << 13) + 2 * m;
    *(__half2*)(g_qh + off) = __halves2half2(__float2half_rn(o0), __float2half_rn(o1));
}

// ---------------------------------------------------------------------------
// Kernel 2: V transpose [h][s][d] fp32 -> V^T [h][d][s] fp16
// ---------------------------------------------------------------------------
__global__ __launch_bounds__(256) void transpose_v(const float* __restrict__ V) {
    __shared__ float tile[32][33];
    int h = blockIdx.z;
    int d0 = blockIdx.x * 32, s0 = blockIdx.y * 32;
    int lx = threadIdx.x & 31, ly = threadIdx.x >> 5;
    const float* src = V + ((long)h << 23);
#pragma unroll
    for (int r = 0; r < 4; r++)
        tile[ly + r * 8][lx] = src[(long)(s0 + ly + r * 8) * Dd + d0 + lx];
    __syncthreads();
    long ob = ((long)h << 23);
#pragma unroll
    for (int r = 0; r < 4; r++) {
        int d = d0 + ly + r * 8;
        g_vt[ob + (long)d * Tt + s0 + lx] = __float2half_rn(tile[lx][ly + r * 8]);
    }
}

// ---------------------------------------------------------------------------
// GEMM core: CTA 128x128, BK=128, 8 warps = 2x2 spatial (64x64) x 2-way ksplit.
// acc[4][8][4]: 4 m16-blocks x 8 n8-blocks. Merge ksplit halves via SMEM.
// ---------------------------------------------------------------------------
__device__ __forceinline__ void ld_tile128(uint32_t sbase, const __half* g, long ld, int tid) {
#pragma unroll
    for (int i = 0; i < 8; i++) {
        int cid = i * 256 + tid;            // 0..2047
        int row = cid >> 4;
        int seg = cid & 15;                 // 16B segment within 256B row
        uint32_t off = (seg >> 3) * SUB_BYTES + SWZ(row, (seg & 7) << 4);
        cp16(sbase + off, g + (long)row * ld + seg * 8);
    }
}

__device__ __forceinline__ void gemm_run(
    const __half* __restrict__ A, long lda,
    const __half* __restrict__ B, long ldb,
    int nch, uint32_t s0, int tid, float acc[4][8][4], bool mma_on)
{
    const int lane = tid & 31, wid = tid >> 5;
    const int sid = wid & 3;                 // spatial quadrant
    const int ks  = wid >> 2;                // k-split half
    const int wm = (sid & 1) * 64, wn = (sid >> 1) * 64;

    // prologue: fill up to 3 stages
#pragma unroll
    for (int s = 0; s < NSTAGE; s++) {
        if (s < nch) {
            uint32_t sb = s0 + s * STAGE_BYTES;
            ld_tile128(sb,              A + s * 128, lda, tid);
            ld_tile128(sb + OPER_BYTES, B + s * 128, ldb, tid);
        }
        CP_COMMIT;
    }

    const int arow = lane & 15;
    const int acb  = (lane >> 4) << 4;
    const int brow = (lane & 7) + ((lane >> 4) << 3);
    const int bcb  = ((lane >> 3) & 1) << 4;
    const uint32_t sub = ks * SUB_BYTES;     // ksplit half = BK sub-tile

    int st = 0;
    for (int kc = 0; kc < nch; kc++) {
        CP_WAIT2;
        __syncthreads();
        uint32_t sb = s0 + st * STAGE_BYTES;
        if (mma_on) {
#pragma unroll
            for (int kb = 0; kb < 4; kb++) {
                int cbk = kb * 32;
                uint32_t a[4][4];
#pragma unroll
                for (int mb = 0; mb < 4; mb++) {
                    int r = wm + mb * 16 + arow;
                    ldsm4(a[mb][0], a[mb][1], a[mb][2], a[mb][3],
                          sb + sub + SWZ(r, cbk + acb));
                }
#pragma unroll
                for (int nb2 = 0; nb2 < 4; nb2++) {
                    int r = wn + nb2 * 16 + brow;
                    uint32_t b0, b1, b2, b3;
                    ldsm4(b0, b1, b2, b3, sb + OPER_BYTES + sub + SWZ(r, cbk + bcb));
#pragma unroll
                    for (int mb = 0; mb < 4; mb++) {
                        mma16816(acc[mb][2 * nb2],     a[mb][0], a[mb][1], a[mb][2], a[mb][3], b0, b1);
                        mma16816(acc[mb][2 * nb2 + 1], a[mb][0], a[mb][1], a[mb][2], a[mb][3], b2, b3);
                    }
                }
            }
        }
        __syncthreads();
        if (kc + NSTAGE < nch) {
            uint32_t sb2 = s0 + st * STAGE_BYTES;
            ld_tile128(sb2,              A + (kc + NSTAGE) * 128, lda, tid);
            ld_tile128(sb2 + OPER_BYTES, B + (kc + NSTAGE) * 128, ldb, tid);
        }
        CP_COMMIT;
        st = (st == NSTAGE - 1) ? 0 : st + 1;
    }

    // merge ksplit halves: warps 4-7 dump acc, warps 0-3 add
    __syncthreads();
    if (ks == 1) {
        char* mbuf = (char*)0;  // placeholder; real pointer passed via s0 smem space
    }
}

// merge + epilogue helpers operate directly in the calling kernels (need dyn ptr)
__device__ __forceinline__ void ksplit_merge(char* dyn, int tid, float acc[4][8][4]) {
    const int lane = tid & 31, wid = tid >> 5;
    const int sid = wid & 3, ks = wid >> 2;
    float4* buf = (float4*)(dyn + sid * 16384);
    __syncthreads();
    if (ks == 1) {
#pragma unroll
        for (int mb = 0; mb < 4; mb++)
#pragma unroll
            for (int nb = 0; nb < 8; nb++)
                buf[(mb * 8 + nb) * 32 + lane] =
                    make_float4(acc[mb][nb][0], acc[mb][nb][1], acc[mb][nb][2], acc[mb][nb][3]);
    }
    __syncthreads();
    if (ks == 0) {
#pragma unroll
        for (int mb = 0; mb < 4; mb++)
#pragma unroll
            for (int nb = 0; nb < 8; nb++) {
                float4 v = buf[(mb * 8 + nb) * 32 + lane];
                acc[mb][nb][0] += v.x; acc[mb][nb][1] += v.y;
                acc[mb][nb][2] += v.z; acc[mb][nb][3] += v.w;
            }
    }
}

// ---------------------------------------------------------------------------
// Kernel 3: scores = mask_strict_lower(Qr Qr^T) * SCALE  (lower-tri tiles only)
// ---------------------------------------------------------------------------
__global__ __launch_bounds__(256, 1) void gemm1_scores() {
    extern __shared__ char dyn[];
    uint32_t s0 = smem_u32(dyn);
    int tid = threadIdx.x;
    int h = blockIdx.y;
    int p = blockIdx.x;
    int bi = 0;
    while ((bi + 1) * (bi + 2) / 2 <= p) ++bi;
    int bj = p - bi * (bi + 1) / 2;

    long qb = ((long)h << 23);
    const __half* A = g_qh + qb + (long)bi * 128 * Dd;
    const __half* B = g_qh + qb + (long)bj * 128 * Dd;

    float acc[4][8][4];
#pragma unroll
    for (int a = 0; a < 4; a++)
#pragma unroll
        for (int b = 0; b < 8; b++)
#pragma unroll
            for (int c = 0; c < 4; c++) acc[a][b][c] = 0.f;

    const int lane = tid & 31, wid = tid >> 5;
    const int sid = wid & 3, ks = wid >> 2;
    const int wm = (sid & 1) * 64, wn = (sid >> 1) * 64;
    bool mma_on = !(bi == bj && wn > wm);   // strictly-upper quadrant of diag tile

    gemm_run(A, Dd, B, Dd, Dd / 128, s0, tid, acc, mma_on);
    ksplit_merge(dyn, tid, acc);

    if (ks == 0) {
        int tr0 = bi * 128 + wm + (lane >> 2);
        int sc0 = bj * 128 + wn + (lane & 3) * 2;
        long hb = (long)h * Tt * Tt;
#pragma unroll
        for (int mb = 0; mb < 4; mb++) {
#pragma unroll
            for (int nb = 0; nb < 8; nb++) {
                int sc = sc0 + nb * 8;
                float* c = acc[mb][nb];
#pragma unroll
                for (int rh = 0; rh < 2; rh++) {
                    int rr = tr0 + mb * 16 + rh * 8;
                    float v0 = (sc     < rr) ? c[rh * 2 + 0] * SCALE : 0.f;
                    float v1 = (sc + 1 < rr) ? c[rh * 2 + 1] * SCALE : 0.f;
                    *(__half2*)(g_sh + hb + (long)rr * Tt + sc) =
                        __halves2half2(__float2half_rn(v0), __float2half_rn(v1));
                }
            }
        }
    }
}

// ---------------------------------------------------------------------------
// Kernel 4: out = scores @ V   (A = scores fp16, B = V^T fp16), causal K
// ---------------------------------------------------------------------------
__global__ __launch_bounds__(256, 1) void gemm2_out(float* __restrict__ O) {
    extern __shared__ char dyn[];
    uint32_t s0 = smem_u32(dyn);
    int tid = threadIdx.x;
    int bn = blockIdx.x;          // d tile 0..63
    int bi = 7 - blockIdx.y;      // t tile, big-K first
    int h  = blockIdx.z;

    const __half* A = g_sh + (long)h * Tt * Tt + (long)bi * 128 * Tt;
    const __half* B = g_vt + ((long)h << 23) + (long)bn * 128 * Tt;

    float acc[4][8][4];
#pragma unroll
    for (int a = 0; a < 4; a++)
#pragma unroll
        for (int b = 0; b < 8; b++)
#pragma unroll
            for (int c = 0; c < 4; c++) acc[a][b][c] = 0.f;

    int nch = bi + 1;   // K = (bi+1)*128, chunks of 128
    gemm_run(A, Tt, B, Tt, nch, s0, tid, acc, true);
    ksplit_merge(dyn, tid, acc);

    const int lane = tid & 31, wid = tid >> 5;
    const int sid = wid & 3, ks = wid >> 2;
    const int wm = (sid & 1) * 64, wn = (sid >> 1) * 64;
    if (ks == 0) {
        int tr0 = bi * 128 + wm + (lane >> 2);
        int dc0 = bn * 128 + wn + (lane & 3) * 2;
        long hb = ((long)h << 23);
#pragma unroll
        for (int mb = 0; mb < 4; mb++) {
#pragma unroll
            for (int nb = 0; nb < 8; nb++) {
                int dc = dc0 + nb * 8;
                float* c = acc[mb][nb];
#pragma unroll
                for (int rh = 0; rh < 2; rh++) {
                    int rr = tr0 + mb * 16 + rh * 8;
                    *(float2*)(O + hb + (long)rr * Dd + dc) =
                        make_float2(c[rh * 2 + 0], c[rh * 2 + 1]);
                }
            }
        }
    }
}

// ---------------------------------------------------------------------------
extern "C" void kernel_launch(void* const* d_in, const int* in_sizes, int n_in,
                              void* d_out, int out_size) {
    (void)in_sizes; (void)n_in; (void)out_size;
    const float* query = (const float*)d_in[0];
    const float* value = (const float*)d_in[1];
    float* out = (float*)d_out;

    const int SMEM_BYTES = NSTAGE * STAGE_BYTES;  // 192 KB
    static int attr_done = 0;
    if (!attr_done) {
        cudaFuncSetAttribute(gemm1_scores, cudaFuncAttributeMaxDynamicSharedMemorySize, SMEM_BYTES);
        cudaFuncSetAttribute(gemm2_out,    cudaFuncAttributeMaxDynamicSharedMemorySize, SMEM_BYTES);
        attr_done = 1;
    }

    rope_kernel<<<65536, 256>>>(query);

    dim3 gt(Dd / 32, Tt / 32, Hh);
    transpose_v<<<gt, 256>>>(value);

    dim3 g1(36, Hh);
    gemm1_scores<<<g1, 256, SMEM_BYTES>>>();

    dim3 g2(Dd / 128, Tt / 128, Hh);
    gemm2_out<<<g2, 256, SMEM_BYTES>>>(out);
}

// round 7
// speedup vs baseline: 1.0537x; 1.0537x over previous
#include <cuda_runtime.h>
#include <cuda_fp16.h>
#include <cstdint>
#include <math.h>

#define Hh 4
#define Tt 1024
#define Dd 8192
#define SCALE 0.011048543456039806f  /* 1/sqrt(8192) */

// ---------------- scratch (static device arrays; no allocation) -------------
__device__ __half g_qh[(size_t)Hh * Tt * Dd];   // 64 MB  rope'd query fp16
__device__ __half g_vt[(size_t)Hh * Dd * Tt];   // 64 MB  V^T [h][d][s] fp16
__device__ __half g_sh[(size_t)Hh * Tt * Tt];   // 8 MB   masked scores fp16

// ---------------- helpers (base-arch PTX only: cp.async/ldmatrix/mma.sync) --
__device__ __forceinline__ uint32_t smem_u32(const void* p) {
    uint32_t a;
    asm("{ .reg .u64 t; cvta.to.shared.u64 t, %1; cvt.u32.u64 %0, t; }" : "=r"(a) : "l"(p));
    return a;
}
__device__ __forceinline__ void cp16(uint32_t dst, const void* src) {
    asm volatile("cp.async.cg.shared.global [%0], [%1], 16;" :: "r"(dst), "l"(src) : "memory");
}
#define CP_COMMIT asm volatile("cp.async.commit_group;" ::: "memory")
#define CP_WAIT1  asm volatile("cp.async.wait_group 1;" ::: "memory")
#define CP_WAIT2  asm volatile("cp.async.wait_group 2;" ::: "memory")

__device__ __forceinline__ void ldsm4(uint32_t& r0, uint32_t& r1, uint32_t& r2, uint32_t& r3,
                                      uint32_t a) {
    asm volatile("ldmatrix.sync.aligned.m8n8.x4.shared.b16 {%0,%1,%2,%3}, [%4];"
                 : "=r"(r0), "=r"(r1), "=r"(r2), "=r"(r3) : "r"(a));
}
__device__ __forceinline__ void mma16816(float* c,
                                         uint32_t a0, uint32_t a1, uint32_t a2, uint32_t a3,
                                         uint32_t b0, uint32_t b1) {
    asm volatile(
        "mma.sync.aligned.m16n8k16.row.col.f32.f16.f16.f32 "
        "{%0,%1,%2,%3},{%4,%5,%6,%7},{%8,%9},{%0,%1,%2,%3};"
        : "+f"(c[0]), "+f"(c[1]), "+f"(c[2]), "+f"(c[3])
        : "r"(a0), "r"(a1), "r"(a2), "r"(a3), "r"(b0), "r"(b1));
}

// 128B rows (64 halves of K per sub-tile), XOR swizzle: conflict-free
#define SWZ(row, cb) ((row) * 128 + ((cb) ^ (((row) & 7) << 4)))

// ---- gemm1 (R5 config): 128x128 tile, BK=128, stage = A 32K | B 32K --------
#define SUB_BYTES   16384
#define OPER_BYTES  32768
#define STAGE1      65536
#define NSTAGE1     3

// ---- gemm2: 128x256 tile, BK=128, stage = A 32K | B 64K --------------------
#define B2_SUB      32768   /* 256 rows x 128B per k-half */
#define STAGE2      98304
#define NSTAGE2     2

// ---------------------------------------------------------------------------
// Kernel 1: bug-faithful ROPE -> fp16
// ---------------------------------------------------------------------------
__global__ void rope_kernel(const float* __restrict__ q) {
    long idx = (long)blockIdx.x * 256 + threadIdx.x;   // pair index
    int m   = (int)(idx & (Dd / 2 - 1));
    int row = (int)(idx >> 12);
    int t = row & (Tt - 1);
    int h = row >> 10;

    const float* qrow = q + ((long)row << 13);
    float v0 = qrow[2 * m];
    float v1 = qrow[2 * m + 1];

    int q2   = t & 1;
    int dsrc = (q2 << 12) + m;
    int tsrc = ((h & 1) << 9) + (t >> 1);
    int h2   = h >> 1;
    const float* base = q + ((long)(2 * h2) << 23);
    float rot0 = -base[(1L << 23) + (long)tsrc * Dd + dsrc];
    float rot1 =  base[(long)tsrc * Dd + dsrc];

    float freq = exp2f(-(float)m * (1.0f / 256.0f)) * 0.15915494309189535f;
    float ph = fmodf((float)t * freq, 1.0f);
    float c = cospif(2.0f * ph);
    float s = sinpif(2.0f * ph);

    float o0 = v0 * c + rot0 * s;
    float o1 = v1 * c + rot1 * s;

    long off = ((long)row << 13) + 2 * m;
    *(__half2*)(g_qh + off) = __halves2half2(__float2half_rn(o0), __float2half_rn(o1));
}

// ---------------------------------------------------------------------------
// Kernel 2: V transpose [h][s][d] fp32 -> V^T [h][d][s] fp16
// ---------------------------------------------------------------------------
__global__ __launch_bounds__(256) void transpose_v(const float* __restrict__ V) {
    __shared__ float tile[32][33];
    int h = blockIdx.z;
    int d0 = blockIdx.x * 32, s0 = blockIdx.y * 32;
    int lx = threadIdx.x & 31, ly = threadIdx.x >> 5;
    const float* src = V + ((long)h << 23);
#pragma unroll
    for (int r = 0; r < 4; r++)
        tile[ly + r * 8][lx] = src[(long)(s0 + ly + r * 8) * Dd + d0 + lx];
    __syncthreads();
    long ob = ((long)h << 23);
#pragma unroll
    for (int r = 0; r < 4; r++) {
        int d = d0 + ly + r * 8;
        g_vt[ob + (long)d * Tt + s0 + lx] = __float2half_rn(tile[lx][ly + r * 8]);
    }
}

// ---------------------------------------------------------------------------
// tile loaders
// ---------------------------------------------------------------------------
__device__ __forceinline__ void ld_tile128(uint32_t sbase, const __half* g, long ld, int tid) {
#pragma unroll
    for (int i = 0; i < 8; i++) {
        int cid = i * 256 + tid;            // 0..2047
        int row = cid >> 4;
        int seg = cid & 15;
        uint32_t off = (seg >> 3) * SUB_BYTES + SWZ(row, (seg & 7) << 4);
        cp16(sbase + off, g + (long)row * ld + seg * 8);
    }
}
__device__ __forceinline__ void ld_tile256(uint32_t sbase, const __half* g, long ld, int tid) {
#pragma unroll
    for (int i = 0; i < 16; i++) {
        int cid = i * 256 + tid;            // 0..4095
        int row = cid >> 4;                 // 0..255
        int seg = cid & 15;
        uint32_t off = (seg >> 3) * B2_SUB + SWZ(row, (seg & 7) << 4);
        cp16(sbase + off, g + (long)row * ld + seg * 8);
    }
}

// ---------------------------------------------------------------------------
// gemm1 core (R5): 8 warps of 32x64, 3-stage ring
// ---------------------------------------------------------------------------
__device__ __forceinline__ void gemm_run1(
    const __half* __restrict__ A, long lda,
    const __half* __restrict__ B, long ldb,
    int nch, uint32_t s0, int tid, float acc[2][8][4], bool mma_on)
{
    const int lane = tid & 31, wid = tid >> 5;
    const int wm = (wid & 3) * 32, wn = (wid >> 2) * 64;

#pragma unroll
    for (int s = 0; s < NSTAGE1; s++) {
        if (s < nch) {
            uint32_t sb = s0 + s * STAGE1;
            ld_tile128(sb,              A + s * 128, lda, tid);
            ld_tile128(sb + OPER_BYTES, B + s * 128, ldb, tid);
        }
        CP_COMMIT;
    }

    const int arow = lane & 15;
    const int acb  = (lane >> 4) << 4;
    const int brow = (lane & 7) + ((lane >> 4) << 3);
    const int bcb  = ((lane >> 3) & 1) << 4;

    int st = 0;
    for (int kc = 0; kc < nch; kc++) {
        CP_WAIT2;
        __syncthreads();
        uint32_t sb = s0 + st * STAGE1;
        if (mma_on) {
#pragma unroll
            for (int kb = 0; kb < 8; kb++) {
                uint32_t sub = (kb >> 2) * SUB_BYTES;
                int cbk = (kb & 3) * 32;
                uint32_t a[2][4];
#pragma unroll
                for (int mb = 0; mb < 2; mb++) {
                    int r = wm + mb * 16 + arow;
                    ldsm4(a[mb][0], a[mb][1], a[mb][2], a[mb][3],
                          sb + sub + SWZ(r, cbk + acb));
                }
#pragma unroll
                for (int nb = 0; nb < 4; nb++) {
                    int r = wn + nb * 16 + brow;
                    uint32_t b0, b1, b2, b3;
                    ldsm4(b0, b1, b2, b3, sb + OPER_BYTES + sub + SWZ(r, cbk + bcb));
#pragma unroll
                    for (int mb = 0; mb < 2; mb++) {
                        mma16816(acc[mb][2 * nb],     a[mb][0], a[mb][1], a[mb][2], a[mb][3], b0, b1);
                        mma16816(acc[mb][2 * nb + 1], a[mb][0], a[mb][1], a[mb][2], a[mb][3], b2, b3);
                    }
                }
            }
        }
        __syncthreads();
        if (kc + NSTAGE1 < nch) {
            uint32_t sb2 = s0 + st * STAGE1;
            ld_tile128(sb2,              A + (kc + NSTAGE1) * 128, lda, tid);
            ld_tile128(sb2 + OPER_BYTES, B + (kc + NSTAGE1) * 128, ldb, tid);
        }
        CP_COMMIT;
        st = (st == NSTAGE1 - 1) ? 0 : st + 1;
    }
}

// ---------------------------------------------------------------------------
// Kernel 3: scores = mask_strict_lower(Qr Qr^T) * SCALE  (R5 config)
// ---------------------------------------------------------------------------
__global__ __launch_bounds__(256, 1) void gemm1_scores() {
    extern __shared__ char dyn[];
    uint32_t s0 = smem_u32(dyn);
    int tid = threadIdx.x;
    int h = blockIdx.y;
    int p = blockIdx.x;
    int bi = 0;
    while ((bi + 1) * (bi + 2) / 2 <= p) ++bi;
    int bj = p - bi * (bi + 1) / 2;

    long qb = ((long)h << 23);
    const __half* A = g_qh + qb + (long)bi * 128 * Dd;
    const __half* B = g_qh + qb + (long)bj * 128 * Dd;

    float acc[2][8][4];
#pragma unroll
    for (int a = 0; a < 2; a++)
#pragma unroll
        for (int b = 0; b < 8; b++)
#pragma unroll
            for (int c = 0; c < 4; c++) acc[a][b][c] = 0.f;

    const int lane = tid & 31, wid = tid >> 5;
    const int wm = (wid & 3) * 32, wn = (wid >> 2) * 64;
    bool mma_on = !(bi == bj && wn >= wm + 32);

    gemm_run1(A, Dd, B, Dd, Dd / 128, s0, tid, acc, mma_on);

    int tr0 = bi * 128 + wm + (lane >> 2);
    int sc0 = bj * 128 + wn + (lane & 3) * 2;
    long hb = (long)h * Tt * Tt;
#pragma unroll
    for (int mb = 0; mb < 2; mb++) {
#pragma unroll
        for (int n8 = 0; n8 < 8; n8++) {
            int sc = sc0 + n8 * 8;
            float* c = acc[mb][n8];
#pragma unroll
            for (int rh = 0; rh < 2; rh++) {
                int rr = tr0 + mb * 16 + rh * 8;
                float v0 = (sc     < rr) ? c[rh * 2 + 0] * SCALE : 0.f;
                float v1 = (sc + 1 < rr) ? c[rh * 2 + 1] * SCALE : 0.f;
                *(__half2*)(g_sh + hb + (long)rr * Tt + sc) =
                    __halves2half2(__float2half_rn(v0), __float2half_rn(v1));
            }
        }
    }
}

// ---------------------------------------------------------------------------
// Kernel 4: out = scores @ V.  CTA 128x256, 8 warps of 64x64, 2-stage ring.
// ---------------------------------------------------------------------------
__global__ __launch_bounds__(256, 1) void gemm2_out(float* __restrict__ O) {
    extern __shared__ char dyn[];
    uint32_t s0 = smem_u32(dyn);
    int tid = threadIdx.x;
    int bn = blockIdx.x;          // d tile 0..31 (256 wide)
    int bi = 7 - blockIdx.y;      // t tile, big-K first
    int h  = blockIdx.z;

    const __half* A = g_sh + (long)h * Tt * Tt + (long)bi * 128 * Tt;
    const __half* B = g_vt + ((long)h << 23) + (long)bn * 256 * Tt;

    const int lane = tid & 31, wid = tid >> 5;
    const int wm = (wid & 1) * 64, wn = (wid >> 1) * 64;

    float acc[4][8][4];
#pragma unroll
    for (int a = 0; a < 4; a++)
#pragma unroll
        for (int b = 0; b < 8; b++)
#pragma unroll
            for (int c = 0; c < 4; c++) acc[a][b][c] = 0.f;

    int nch = bi + 1;   // K = (bi+1)*128

    // prologue: 2 stages
#pragma unroll
    for (int s = 0; s < NSTAGE2; s++) {
        if (s < nch) {
            uint32_t sb = s0 + s * STAGE2;
            ld_tile128(sb,              A + s * 128, Tt, tid);
            ld_tile256(sb + OPER_BYTES, B + s * 128, Tt, tid);
        }
        CP_COMMIT;
    }

    const int arow = lane & 15;
    const int acb  = (lane >> 4) << 4;
    const int brow = (lane & 7) + ((lane >> 4) << 3);
    const int bcb  = ((lane >> 3) & 1) << 4;

    for (int kc = 0; kc < nch; kc++) {
        CP_WAIT1;
        __syncthreads();
        uint32_t sb = s0 + (kc & 1) * STAGE2;
#pragma unroll
        for (int kb = 0; kb < 8; kb++) {
            uint32_t suba = (kb >> 2) * SUB_BYTES;
            uint32_t subb = (kb >> 2) * B2_SUB;
            int cbk = (kb & 3) * 32;
            uint32_t a[4][4];
#pragma unroll
            for (int mb = 0; mb < 4; mb++) {
                int r = wm + mb * 16 + arow;
                ldsm4(a[mb][0], a[mb][1], a[mb][2], a[mb][3],
                      sb + suba + SWZ(r, cbk + acb));
            }
#pragma unroll
            for (int nb = 0; nb < 4; nb++) {
                int r = wn + nb * 16 + brow;
                uint32_t b0, b1, b2, b3;
                ldsm4(b0, b1, b2, b3, sb + OPER_BYTES + subb + SWZ(r, cbk + bcb));
#pragma unroll
                for (int mb = 0; mb < 4; mb++) {
                    mma16816(acc[mb][2 * nb],     a[mb][0], a[mb][1], a[mb][2], a[mb][3], b0, b1);
                    mma16816(acc[mb][2 * nb + 1], a[mb][0], a[mb][1], a[mb][2], a[mb][3], b2, b3);
                }
            }
        }
        __syncthreads();
        if (kc + NSTAGE2 < nch) {
            uint32_t sb2 = s0 + (kc & 1) * STAGE2;
            ld_tile128(sb2,              A + (kc + NSTAGE2) * 128, Tt, tid);
            ld_tile256(sb2 + OPER_BYTES, B + (kc + NSTAGE2) * 128, Tt, tid);
        }
        CP_COMMIT;
    }

    int tr0 = bi * 128 + wm + (lane >> 2);
    int dc0 = bn * 256 + wn + (lane & 3) * 2;
    long hb = ((long)h << 23);
#pragma unroll
    for (int mb = 0; mb < 4; mb++) {
#pragma unroll
        for (int nb = 0; nb < 8; nb++) {
            int dc = dc0 + nb * 8;
            float* c = acc[mb][nb];
#pragma unroll
            for (int rh = 0; rh < 2; rh++) {
                int rr = tr0 + mb * 16 + rh * 8;
                *(float2*)(O + hb + (long)rr * Dd + dc) =
                    make_float2(c[rh * 2 + 0], c[rh * 2 + 1]);
            }
        }
    }
}

// ---------------------------------------------------------------------------
extern "C" void kernel_launch(void* const* d_in, const int* in_sizes, int n_in,
                              void* d_out, int out_size) {
    (void)in_sizes; (void)n_in; (void)out_size;
    const float* query = (const float*)d_in[0];
    const float* value = (const float*)d_in[1];
    float* out = (float*)d_out;

    const int SMEM1 = NSTAGE1 * STAGE1;   // 192 KB
    const int SMEM2 = NSTAGE2 * STAGE2;   // 192 KB
    static int attr_done = 0;
    if (!attr_done) {
        cudaFuncSetAttribute(gemm1_scores, cudaFuncAttributeMaxDynamicSharedMemorySize, SMEM1);
        cudaFuncSetAttribute(gemm2_out,    cudaFuncAttributeMaxDynamicSharedMemorySize, SMEM2);
        attr_done = 1;
    }

    rope_kernel<<<65536, 256>>>(query);

    dim3 gt(Dd / 32, Tt / 32, Hh);
    transpose_v<<<gt, 256>>>(value);

    dim3 g1(36, Hh);
    gemm1_scores<<<g1, 256, SMEM1>>>();

    dim3 g2(Dd / 256, Tt / 128, Hh);
    gemm2_out<<<g2, 256, SMEM2>>>(out);
}

// round 8
// speedup vs baseline: 1.0962x; 1.0404x over previous
#include <cuda_runtime.h>
#include <cuda_fp16.h>
#include <cstdint>
#include <math.h>

#define Hh 4
#define Tt 1024
#define Dd 8192
#define SCALE 0.011048543456039806f  /* 1/sqrt(8192) */

// ---------------- scratch (static device arrays; no allocation) -------------
__device__ __half g_qh[(size_t)Hh * Tt * Dd];        // 64 MB  rope'd query fp16
__device__ __half g_vt[(size_t)Hh * Dd * Tt];        // 64 MB  V^T [h][d][s]
__device__ __half g_sh[(size_t)Hh * Tt * Tt];        // 8 MB   masked scores fp16
__device__ float  g_part[2][Hh][36][128 * 128];      // 18.9 MB gemm1 k-split partials

// ---------------- helpers (base-arch PTX only) ------------------------------
__device__ __forceinline__ uint32_t smem_u32(const void* p) {
    uint32_t a;
    asm("{ .reg .u64 t; cvta.to.shared.u64 t, %1; cvt.u32.u64 %0, t; }" : "=r"(a) : "l"(p));
    return a;
}
__device__ __forceinline__ void cp16(uint32_t dst, const void* src) {
    asm volatile("cp.async.cg.shared.global [%0], [%1], 16;" :: "r"(dst), "l"(src) : "memory");
}
#define CP_COMMIT asm volatile("cp.async.commit_group;" ::: "memory")
#define CP_WAIT2  asm volatile("cp.async.wait_group 2;" ::: "memory")

__device__ __forceinline__ void ldsm4(uint32_t& r0, uint32_t& r1, uint32_t& r2, uint32_t& r3,
                                      uint32_t a) {
    asm volatile("ldmatrix.sync.aligned.m8n8.x4.shared.b16 {%0,%1,%2,%3}, [%4];"
                 : "=r"(r0), "=r"(r1), "=r"(r2), "=r"(r3) : "r"(a));
}
__device__ __forceinline__ void mma16816(float* c,
                                         uint32_t a0, uint32_t a1, uint32_t a2, uint32_t a3,
                                         uint32_t b0, uint32_t b1) {
    asm volatile(
        "mma.sync.aligned.m16n8k16.row.col.f32.f16.f16.f32 "
        "{%0,%1,%2,%3},{%4,%5,%6,%7},{%8,%9},{%0,%1,%2,%3};"
        : "+f"(c[0]), "+f"(c[1]), "+f"(c[2]), "+f"(c[3])
        : "r"(a0), "r"(a1), "r"(a2), "r"(a3), "r"(b0), "r"(b1));
}

// 128B rows, XOR swizzle: conflict-free ldmatrix + cp.async
#define SWZ(row, cb) ((row) * 128 + ((cb) ^ (((row) & 7) << 4)))

// BK=64: operand tile = 128 rows x 128B = 16 KB
#define OPER_B   16384
#define STAGE    32768   /* A | B */
#define NST      3       /* 96 KB/CTA -> 2 CTA/SM */

// ---------------------------------------------------------------------------
// Kernel 1: bug-faithful ROPE -> fp16 (2 pairs per thread, float4 reads)
// ---------------------------------------------------------------------------
__global__ void rope_kernel(const float* __restrict__ q) {
    long idx = (long)blockIdx.x * 256 + threadIdx.x;   // 2^23 double-pair idx
    int m2  = (int)(idx & (Dd / 4 - 1));               // 0..2047
    int row = (int)(idx >> 11);                        // h*T + t
    int t = row & (Tt - 1);
    int h = row >> 10;

    const float* qrow = q + ((long)row << 13);
    float4 v = *(const float4*)(qrow + 4 * m2);

    int m0   = 2 * m2;
    int q2   = t & 1;
    int dsrc = (q2 << 12) + m0;
    int tsrc = ((h & 1) << 9) + (t >> 1);
    int h2   = h >> 1;
    const float* base = q + ((long)(2 * h2) << 23);
    float2 rA = *(const float2*)(base + (1L << 23) + (long)tsrc * Dd + dsrc); // j=0 src (negate)
    float2 rB = *(const float2*)(base + (long)tsrc * Dd + dsrc);              // j=1 src

    const float inv2pi = 0.15915494309189535f;
    float f0 = exp2f(-(float)m0 * (1.0f / 256.0f)) * inv2pi;
    float f1 = exp2f(-(float)(m0 + 1) * (1.0f / 256.0f)) * inv2pi;
    float p0 = fmodf((float)t * f0, 1.0f);
    float p1 = fmodf((float)t * f1, 1.0f);
    float c0 = cospif(2.0f * p0), s0 = sinpif(2.0f * p0);
    float c1 = cospif(2.0f * p1), s1 = sinpif(2.0f * p1);

    float o0 = v.x * c0 - rA.x * s0;
    float o1 = v.y * c0 + rB.x * s0;
    float o2 = v.z * c1 - rA.y * s1;
    float o3 = v.w * c1 + rB.y * s1;

    __half2 w0 = __halves2half2(__float2half_rn(o0), __float2half_rn(o1));
    __half2 w1 = __halves2half2(__float2half_rn(o2), __float2half_rn(o3));
    uint2 pk;
    pk.x = *(uint32_t*)&w0;
    pk.y = *(uint32_t*)&w1;
    *(uint2*)(g_qh + ((long)row << 13) + 4 * m2) = pk;
}

// ---------------------------------------------------------------------------
// Kernel 2: V transpose [h][s][d] fp32 -> V^T [h][d][s] fp16
// ---------------------------------------------------------------------------
__global__ __launch_bounds__(256) void transpose_v(const float* __restrict__ V) {
    __shared__ float tile[32][33];
    int h = blockIdx.z;
    int d0 = blockIdx.x * 32, s0 = blockIdx.y * 32;
    int lx = threadIdx.x & 31, ly = threadIdx.x >> 5;
    const float* src = V + ((long)h << 23);
#pragma unroll
    for (int r = 0; r < 4; r++)
        tile[ly + r * 8][lx] = src[(long)(s0 + ly + r * 8) * Dd + d0 + lx];
    __syncthreads();
    long ob = ((long)h << 23);
#pragma unroll
    for (int r = 0; r < 4; r++) {
        int d = d0 + ly + r * 8;
        g_vt[ob + (long)d * Tt + s0 + lx] = __float2half_rn(tile[lx][ly + r * 8]);
    }
}

// ---------------------------------------------------------------------------
// Shared GEMM core: CTA 128x128, 4 warps of 64x64, BK=64, 3-stage ring.
// ---------------------------------------------------------------------------
__device__ __forceinline__ void ld_tile64(uint32_t sbase, const __half* g, long ld, int tid) {
#pragma unroll
    for (int i = 0; i < 8; i++) {
        int cid = i * 128 + tid;            // 0..1023
        int row = cid >> 3;
        int seg = cid & 7;
        cp16(sbase + SWZ(row, seg << 4), g + (long)row * ld + seg * 8);
    }
}

__device__ __forceinline__ void gemm_run4(
    const __half* __restrict__ A, long lda,
    const __half* __restrict__ B, long ldb,
    int nch, uint32_t s0, int tid, float acc[4][8][4], bool mma_on)
{
    const int lane = tid & 31, wid = tid >> 5;
    const int wm = (wid & 1) * 64, wn = (wid >> 1) * 64;

#pragma unroll
    for (int s = 0; s < NST; s++) {
        if (s < nch) {
            uint32_t sb = s0 + s * STAGE;
            ld_tile64(sb,          A + s * 64, lda, tid);
            ld_tile64(sb + OPER_B, B + s * 64, ldb, tid);
        }
        CP_COMMIT;
    }

    const int arow = lane & 15;
    const int acb  = (lane >> 4) << 4;
    const int brow = (lane & 7) + ((lane >> 4) << 3);
    const int bcb  = ((lane >> 3) & 1) << 4;

    int st = 0;
    for (int kc = 0; kc < nch; kc++) {
        CP_WAIT2;
        __syncthreads();
        uint32_t sb = s0 + st * STAGE;
        if (mma_on) {
#pragma unroll
            for (int kb = 0; kb < 4; kb++) {
                int cbk = kb * 32;
                uint32_t a[4][4];
#pragma unroll
                for (int mb = 0; mb < 4; mb++) {
                    int r = wm + mb * 16 + arow;
                    ldsm4(a[mb][0], a[mb][1], a[mb][2], a[mb][3],
                          sb + SWZ(r, cbk + acb));
                }
#pragma unroll
                for (int nb = 0; nb < 4; nb++) {
                    int r = wn + nb * 16 + brow;
                    uint32_t b0, b1, b2, b3;
                    ldsm4(b0, b1, b2, b3, sb + OPER_B + SWZ(r, cbk + bcb));
#pragma unroll
                    for (int mb = 0; mb < 4; mb++) {
                        mma16816(acc[mb][2 * nb],     a[mb][0], a[mb][1], a[mb][2], a[mb][3], b0, b1);
                        mma16816(acc[mb][2 * nb + 1], a[mb][0], a[mb][1], a[mb][2], a[mb][3], b2, b3);
                    }
                }
            }
        }
        __syncthreads();
        if (kc + NST < nch) {
            uint32_t sb2 = s0 + st * STAGE;
            ld_tile64(sb2,          A + (kc + NST) * 64, lda, tid);
            ld_tile64(sb2 + OPER_B, B + (kc + NST) * 64, ldb, tid);
        }
        CP_COMMIT;
        st = (st == NST - 1) ? 0 : st + 1;
    }
}

// ---------------------------------------------------------------------------
// Kernel 3: gemm1 k-split partials: part[ks] = Q[bi] @ Q[bj]^T over K half
// ---------------------------------------------------------------------------
__global__ __launch_bounds__(128, 2) void gemm1_partial() {
    extern __shared__ char dyn[];
    uint32_t s0 = smem_u32(dyn);
    int tid = threadIdx.x;
    int p  = blockIdx.x;   // 0..35 lower-tri tile
    int ks = blockIdx.y;   // k half
    int h  = blockIdx.z;
    int bi = 0;
    while ((bi + 1) * (bi + 2) / 2 <= p) ++bi;
    int bj = p - bi * (bi + 1) / 2;

    long qb = ((long)h << 23) + (long)ks * (Dd / 2);
    const __half* A = g_qh + qb + (long)bi * 128 * Dd;
    const __half* B = g_qh + qb + (long)bj * 128 * Dd;

    float acc[4][8][4];
#pragma unroll
    for (int a = 0; a < 4; a++)
#pragma unroll
        for (int b = 0; b < 8; b++)
#pragma unroll
            for (int c = 0; c < 4; c++) acc[a][b][c] = 0.f;

    const int lane = tid & 31, wid = tid >> 5;
    const int wm = (wid & 1) * 64, wn = (wid >> 1) * 64;
    bool mma_on = !(bi == bj && wn > wm);   // fully-masked quadrant of diag tile

    gemm_run4(A, Dd, B, Dd, Dd / 2 / 64, s0, tid, acc, mma_on);

    float* C = g_part[ks][h][p];
    int r0 = wm + (lane >> 2);
    int c0 = wn + (lane & 3) * 2;
#pragma unroll
    for (int mb = 0; mb < 4; mb++) {
#pragma unroll
        for (int nb = 0; nb < 8; nb++) {
            float* c = acc[mb][nb];
#pragma unroll
            for (int rh = 0; rh < 2; rh++) {
                int rr = r0 + mb * 16 + rh * 8;
                *(float2*)(C + rr * 128 + c0 + nb * 8) =
                    make_float2(c[rh * 2 + 0], c[rh * 2 + 1]);
            }
        }
    }
}

// ---------------------------------------------------------------------------
// Kernel 3b: merge partials -> masked scaled fp16 scores
// ---------------------------------------------------------------------------
__global__ __launch_bounds__(256) void merge_scores() {
    int p = blockIdx.x;   // 0..35
    int h = blockIdx.y;
    int bi = 0;
    while ((bi + 1) * (bi + 2) / 2 <= p) ++bi;
    int bj = p - bi * (bi + 1) / 2;

    const float* P0 = g_part[0][h][p];
    const float* P1 = g_part[1][h][p];
    long hb = (long)h * Tt * Tt;

#pragma unroll
    for (int e = 0; e < 32; e++) {
        int i2 = e * 256 + threadIdx.x;       // 0..8191 (pairs)
        int r = i2 >> 6;                      // 0..127
        int cpair = (i2 & 63) * 2;            // 0..126
        float2 a = *(const float2*)(P0 + r * 128 + cpair);
        float2 b = *(const float2*)(P1 + r * 128 + cpair);
        int t = bi * 128 + r;
        int s = bj * 128 + cpair;
        float v0 = (s     < t) ? (a.x + b.x) * SCALE : 0.f;
        float v1 = (s + 1 < t) ? (a.y + b.y) * SCALE : 0.f;
        *(__half2*)(g_sh + hb + (long)t * Tt + s) =
            __halves2half2(__float2half_rn(v0), __float2half_rn(v1));
    }
}

// ---------------------------------------------------------------------------
// Kernel 4: out = scores @ V  (causal K), 4-warp CTA, 2/SM
// ---------------------------------------------------------------------------
__global__ __launch_bounds__(128, 2) void gemm2_out(float* __restrict__ O) {
    extern __shared__ char dyn[];
    uint32_t s0 = smem_u32(dyn);
    int tid = threadIdx.x;
    int bn = blockIdx.x;          // d tile 0..63
    int bi = 7 - blockIdx.y;      // t tile, big-K first
    int h  = blockIdx.z;

    const __half* A = g_sh + (long)h * Tt * Tt + (long)bi * 128 * Tt;
    const __half* B = g_vt + ((long)h << 23) + (long)bn * 128 * Tt;

    float acc[4][8][4];
#pragma unroll
    for (int a = 0; a < 4; a++)
#pragma unroll
        for (int b = 0; b < 8; b++)
#pragma unroll
            for (int c = 0; c < 4; c++) acc[a][b][c] = 0.f;

    int nch = (bi + 1) * 2;   // K = (bi+1)*128, BK=64
    gemm_run4(A, Tt, B, Tt, nch, s0, tid, acc, true);

    const int lane = tid & 31, wid = tid >> 5;
    const int wm = (wid & 1) * 64, wn = (wid >> 1) * 64;
    int tr0 = bi * 128 + wm + (lane >> 2);
    int dc0 = bn * 128 + wn + (lane & 3) * 2;
    long hb = ((long)h << 23);
#pragma unroll
    for (int mb = 0; mb < 4; mb++) {
#pragma unroll
        for (int nb = 0; nb < 8; nb++) {
            int dc = dc0 + nb * 8;
            float* c = acc[mb][nb];
#pragma unroll
            for (int rh = 0; rh < 2; rh++) {
                int rr = tr0 + mb * 16 + rh * 8;
                *(float2*)(O + hb + (long)rr * Dd + dc) =
                    make_float2(c[rh * 2 + 0], c[rh * 2 + 1]);
            }
        }
    }
}

// ---------------------------------------------------------------------------
extern "C" void kernel_launch(void* const* d_in, const int* in_sizes, int n_in,
                              void* d_out, int out_size) {
    (void)in_sizes; (void)n_in; (void)out_size;
    const float* query = (const float*)d_in[0];
    const float* value = (const float*)d_in[1];
    float* out = (float*)d_out;

    const int SMEM_BYTES = NST * STAGE;   // 96 KB per CTA
    static int attr_done = 0;
    if (!attr_done) {
        cudaFuncSetAttribute(gemm1_partial, cudaFuncAttributeMaxDynamicSharedMemorySize, SMEM_BYTES);
        cudaFuncSetAttribute(gemm2_out,     cudaFuncAttributeMaxDynamicSharedMemorySize, SMEM_BYTES);
        attr_done = 1;
    }

    rope_kernel<<<32768, 256>>>(query);

    dim3 gt(Dd / 32, Tt / 32, Hh);
    transpose_v<<<gt, 256>>>(value);

    dim3 g1(36, 2, Hh);
    gemm1_partial<<<g1, 128, SMEM_BYTES>>>();

    dim3 gm(36, Hh);
    merge_scores<<<gm, 256>>>();

    dim3 g2(Dd / 128, Tt / 128, Hh);
    gemm2_out<<<g2, 128, SMEM_BYTES>>>(out);
}

// round 9
// speedup vs baseline: 1.1233x; 1.0247x over previous
#include <cuda_runtime.h>
#include <cuda_fp16.h>
#include <cstdint>
#include <math.h>

#define Hh 4
#define Tt 1024
#define Dd 8192
#define SCALE 0.011048543456039806f  /* 1/sqrt(8192) */

// ---------------- scratch (static device arrays; no allocation) -------------
__device__ __half g_qh[(size_t)Hh * Tt * Dd];        // 64 MB  rope'd query fp16
__device__ __half g_vt[(size_t)Hh * Dd * Tt];        // 64 MB  V^T [h][d][s]
__device__ __half g_sh[(size_t)Hh * Tt * Tt];        // 8 MB   masked scores fp16
__device__ float  g_part[2][Hh][36][128 * 128];      // 18.9 MB gemm1 k-split partials

// ---------------- helpers (base-arch PTX only) ------------------------------
__device__ __forceinline__ uint32_t smem_u32(const void* p) {
    uint32_t a;
    asm("{ .reg .u64 t; cvta.to.shared.u64 t, %1; cvt.u32.u64 %0, t; }" : "=r"(a) : "l"(p));
    return a;
}
__device__ __forceinline__ void cp16(uint32_t dst, const void* src) {
    asm volatile("cp.async.cg.shared.global [%0], [%1], 16;" :: "r"(dst), "l"(src) : "memory");
}
#define CP_COMMIT asm volatile("cp.async.commit_group;" ::: "memory")
#define CP_WAIT2  asm volatile("cp.async.wait_group 2;" ::: "memory")

__device__ __forceinline__ void ldsm4(uint32_t& r0, uint32_t& r1, uint32_t& r2, uint32_t& r3,
                                      uint32_t a) {
    asm volatile("ldmatrix.sync.aligned.m8n8.x4.shared.b16 {%0,%1,%2,%3}, [%4];"
                 : "=r"(r0), "=r"(r1), "=r"(r2), "=r"(r3) : "r"(a));
}
__device__ __forceinline__ void mma16816(float* c,
                                         uint32_t a0, uint32_t a1, uint32_t a2, uint32_t a3,
                                         uint32_t b0, uint32_t b1) {
    asm volatile(
        "mma.sync.aligned.m16n8k16.row.col.f32.f16.f16.f32 "
        "{%0,%1,%2,%3},{%4,%5,%6,%7},{%8,%9},{%0,%1,%2,%3};"
        : "+f"(c[0]), "+f"(c[1]), "+f"(c[2]), "+f"(c[3])
        : "r"(a0), "r"(a1), "r"(a2), "r"(a3), "r"(b0), "r"(b1));
}

// 128B rows, XOR swizzle: conflict-free ldmatrix + cp.async
#define SWZ(row, cb) ((row) * 128 + ((cb) ^ (((row) & 7) << 4)))

// BK=64: operand tile = 128 rows x 128B = 16 KB
#define OPER_B   16384
#define STAGE    32768   /* A | B */
#define NST      3       /* 96 KB/CTA -> 2 CTA/SM */

// ---------------------------------------------------------------------------
// Kernel 1: bug-faithful ROPE -> fp16 (2 pairs per thread, float4 reads)
// ---------------------------------------------------------------------------
__global__ void rope_kernel(const float* __restrict__ q) {
    long idx = (long)blockIdx.x * 256 + threadIdx.x;   // 2^23 double-pair idx
    int m2  = (int)(idx & (Dd / 4 - 1));               // 0..2047
    int row = (int)(idx >> 11);                        // h*T + t
    int t = row & (Tt - 1);
    int h = row >> 10;

    const float* qrow = q + ((long)row << 13);
    float4 v = *(const float4*)(qrow + 4 * m2);

    int m0   = 2 * m2;
    int q2   = t & 1;
    int dsrc = (q2 << 12) + m0;
    int tsrc = ((h & 1) << 9) + (t >> 1);
    int h2   = h >> 1;
    const float* base = q + ((long)(2 * h2) << 23);
    float2 rA = *(const float2*)(base + (1L << 23) + (long)tsrc * Dd + dsrc); // j=0 src (negate)
    float2 rB = *(const float2*)(base + (long)tsrc * Dd + dsrc);              // j=1 src

    const float inv2pi = 0.15915494309189535f;
    float f0 = exp2f(-(float)m0 * (1.0f / 256.0f)) * inv2pi;
    float f1 = exp2f(-(float)(m0 + 1) * (1.0f / 256.0f)) * inv2pi;
    float p0 = fmodf((float)t * f0, 1.0f);
    float p1 = fmodf((float)t * f1, 1.0f);
    float c0 = cospif(2.0f * p0), s0 = sinpif(2.0f * p0);
    float c1 = cospif(2.0f * p1), s1 = sinpif(2.0f * p1);

    float o0 = v.x * c0 - rA.x * s0;
    float o1 = v.y * c0 + rB.x * s0;
    float o2 = v.z * c1 - rA.y * s1;
    float o3 = v.w * c1 + rB.y * s1;

    __half2 w0 = __halves2half2(__float2half_rn(o0), __float2half_rn(o1));
    __half2 w1 = __halves2half2(__float2half_rn(o2), __float2half_rn(o3));
    uint2 pk;
    pk.x = *(uint32_t*)&w0;
    pk.y = *(uint32_t*)&w1;
    *(uint2*)(g_qh + ((long)row << 13) + 4 * m2) = pk;
}

// ---------------------------------------------------------------------------
// Kernel 2: V transpose [h][s][d] fp32 -> V^T [h][d][s] fp16
// ---------------------------------------------------------------------------
__global__ __launch_bounds__(256) void transpose_v(const float* __restrict__ V) {
    __shared__ float tile[32][33];
    int h = blockIdx.z;
    int d0 = blockIdx.x * 32, s0 = blockIdx.y * 32;
    int lx = threadIdx.x & 31, ly = threadIdx.x >> 5;
    const float* src = V + ((long)h << 23);
#pragma unroll
    for (int r = 0; r < 4; r++)
        tile[ly + r * 8][lx] = src[(long)(s0 + ly + r * 8) * Dd + d0 + lx];
    __syncthreads();
    long ob = ((long)h << 23);
#pragma unroll
    for (int r = 0; r < 4; r++) {
        int d = d0 + ly + r * 8;
        g_vt[ob + (long)d * Tt + s0 + lx] = __float2half_rn(tile[lx][ly + r * 8]);
    }
}

// ---------------------------------------------------------------------------
// Shared GEMM core: CTA 128x128, 4 warps of 64x64, BK=64, 3-stage ring.
// ---------------------------------------------------------------------------
__device__ __forceinline__ void ld_tile64(uint32_t sbase, const __half* g, long ld, int tid) {
#pragma unroll
    for (int i = 0; i < 8; i++) {
        int cid = i * 128 + tid;            // 0..1023
        int row = cid >> 3;
        int seg = cid & 7;
        cp16(sbase + SWZ(row, seg << 4), g + (long)row * ld + seg * 8);
    }
}

__device__ __forceinline__ void gemm_run4(
    const __half* __restrict__ A, long lda,
    const __half* __restrict__ B, long ldb,
    int nch, uint32_t s0, int tid, float acc[4][8][4], bool mma_on)
{
    const int lane = tid & 31, wid = tid >> 5;
    const int wm = (wid & 1) * 64, wn = (wid >> 1) * 64;

#pragma unroll
    for (int s = 0; s < NST; s++) {
        if (s < nch) {
            uint32_t sb = s0 + s * STAGE;
            ld_tile64(sb,          A + s * 64, lda, tid);
            ld_tile64(sb + OPER_B, B + s * 64, ldb, tid);
        }
        CP_COMMIT;
    }

    const int arow = lane & 15;
    const int acb  = (lane >> 4) << 4;
    const int brow = (lane & 7) + ((lane >> 4) << 3);
    const int bcb  = ((lane >> 3) & 1) << 4;

    int st = 0;
    for (int kc = 0; kc < nch; kc++) {
        CP_WAIT2;
        __syncthreads();
        uint32_t sb = s0 + st * STAGE;
        if (mma_on) {
#pragma unroll
            for (int kb = 0; kb < 4; kb++) {
                int cbk = kb * 32;
                uint32_t a[4][4];
#pragma unroll
                for (int mb = 0; mb < 4; mb++) {
                    int r = wm + mb * 16 + arow;
                    ldsm4(a[mb][0], a[mb][1], a[mb][2], a[mb][3],
                          sb + SWZ(r, cbk + acb));
                }
#pragma unroll
                for (int nb = 0; nb < 4; nb++) {
                    int r = wn + nb * 16 + brow;
                    uint32_t b0, b1, b2, b3;
                    ldsm4(b0, b1, b2, b3, sb + OPER_B + SWZ(r, cbk + bcb));
#pragma unroll
                    for (int mb = 0; mb < 4; mb++) {
                        mma16816(acc[mb][2 * nb],     a[mb][0], a[mb][1], a[mb][2], a[mb][3], b0, b1);
                        mma16816(acc[mb][2 * nb + 1], a[mb][0], a[mb][1], a[mb][2], a[mb][3], b2, b3);
                    }
                }
            }
        }
        __syncthreads();
        if (kc + NST < nch) {
            uint32_t sb2 = s0 + st * STAGE;
            ld_tile64(sb2,          A + (kc + NST) * 64, lda, tid);
            ld_tile64(sb2 + OPER_B, B + (kc + NST) * 64, ldb, tid);
        }
        CP_COMMIT;
        st = (st == NST - 1) ? 0 : st + 1;
    }
}

// ---------------------------------------------------------------------------
// Kernel 3: gemm1 k-split partials: part[ks] = Q[bi] @ Q[bj]^T over K half
// ---------------------------------------------------------------------------
__global__ __launch_bounds__(128, 2) void gemm1_partial() {
    extern __shared__ char dyn[];
    uint32_t s0 = smem_u32(dyn);
    int tid = threadIdx.x;
    int p  = blockIdx.x;   // 0..35 lower-tri tile
    int ks = blockIdx.y;   // k half
    int h  = blockIdx.z;
    int bi = 0;
    while ((bi + 1) * (bi + 2) / 2 <= p) ++bi;
    int bj = p - bi * (bi + 1) / 2;

    long qb = ((long)h << 23) + (long)ks * (Dd / 2);
    const __half* A = g_qh + qb + (long)bi * 128 * Dd;
    const __half* B = g_qh + qb + (long)bj * 128 * Dd;

    float acc[4][8][4];
#pragma unroll
    for (int a = 0; a < 4; a++)
#pragma unroll
        for (int b = 0; b < 8; b++)
#pragma unroll
            for (int c = 0; c < 4; c++) acc[a][b][c] = 0.f;

    const int lane = tid & 31, wid = tid >> 5;
    const int wm = (wid & 1) * 64, wn = (wid >> 1) * 64;
    bool mma_on = !(bi == bj && wn > wm);   // fully-masked quadrant of diag tile

    gemm_run4(A, Dd, B, Dd, Dd / 2 / 64, s0, tid, acc, mma_on);

    float* C = g_part[ks][h][p];
    int r0 = wm + (lane >> 2);
    int c0 = wn + (lane & 3) * 2;
#pragma unroll
    for (int mb = 0; mb < 4; mb++) {
#pragma unroll
        for (int nb = 0; nb < 8; nb++) {
            float* c = acc[mb][nb];
#pragma unroll
            for (int rh = 0; rh < 2; rh++) {
                int rr = r0 + mb * 16 + rh * 8;
                *(float2*)(C + rr * 128 + c0 + nb * 8) =
                    make_float2(c[rh * 2 + 0], c[rh * 2 + 1]);
            }
        }
    }
}

// ---------------------------------------------------------------------------
// Kernel 3b: merge partials -> masked scaled fp16 scores (8 slices per tile)
// ---------------------------------------------------------------------------
__global__ __launch_bounds__(256) void merge_scores() {
    int blk = blockIdx.x;          // 0..287 : tile p = blk>>3, slice = blk&7
    int p = blk >> 3;
    int sl = blk & 7;
    int h = blockIdx.y;
    int bi = 0;
    while ((bi + 1) * (bi + 2) / 2 <= p) ++bi;
    int bj = p - bi * (bi + 1) / 2;

    const float* P0 = g_part[0][h][p] + sl * 16 * 128;
    const float* P1 = g_part[1][h][p] + sl * 16 * 128;
    long hb = (long)h * Tt * Tt;
    int trow0 = bi * 128 + sl * 16;

#pragma unroll
    for (int e = 0; e < 4; e++) {
        int i2 = e * 256 + threadIdx.x;       // 0..1023 (pairs in 16x128 slice)
        int r = i2 >> 6;                      // 0..15
        int cpair = (i2 & 63) * 2;            // 0..126
        float2 a = *(const float2*)(P0 + r * 128 + cpair);
        float2 b = *(const float2*)(P1 + r * 128 + cpair);
        int t = trow0 + r;
        int s = bj * 128 + cpair;
        float v0 = (s     < t) ? (a.x + b.x) * SCALE : 0.f;
        float v1 = (s + 1 < t) ? (a.y + b.y) * SCALE : 0.f;
        *(__half2*)(g_sh + hb + (long)t * Tt + s) =
            __halves2half2(__float2half_rn(v0), __float2half_rn(v1));
    }
}

// ---------------------------------------------------------------------------
// Kernel 4: out = scores @ V  (causal K), 4-warp CTA, 2/SM
// ---------------------------------------------------------------------------
__global__ __launch_bounds__(128, 2) void gemm2_out(float* __restrict__ O) {
    extern __shared__ char dyn[];
    uint32_t s0 = smem_u32(dyn);
    int tid = threadIdx.x;
    int bn = blockIdx.x;          // d tile 0..63
    int bi = 7 - blockIdx.y;      // t tile, big-K first
    int h  = blockIdx.z;

    const __half* A = g_sh + (long)h * Tt * Tt + (long)bi * 128 * Tt;
    const __half* B = g_vt + ((long)h << 23) + (long)bn * 128 * Tt;

    float acc[4][8][4];
#pragma unroll
    for (int a = 0; a < 4; a++)
#pragma unroll
        for (int b = 0; b < 8; b++)
#pragma unroll
            for (int c = 0; c < 4; c++) acc[a][b][c] = 0.f;

    int nch = (bi + 1) * 2;   // K = (bi+1)*128, BK=64
    gemm_run4(A, Tt, B, Tt, nch, s0, tid, acc, true);

    const int lane = tid & 31, wid = tid >> 5;
    const int wm = (wid & 1) * 64, wn = (wid >> 1) * 64;
    int tr0 = bi * 128 + wm + (lane >> 2);
    int dc0 = bn * 128 + wn + (lane & 3) * 2;
    long hb = ((long)h << 23);
#pragma unroll
    for (int mb = 0; mb < 4; mb++) {
#pragma unroll
        for (int nb = 0; nb < 8; nb++) {
            int dc = dc0 + nb * 8;
            float* c = acc[mb][nb];
#pragma unroll
            for (int rh = 0; rh < 2; rh++) {
                int rr = tr0 + mb * 16 + rh * 8;
                *(float2*)(O + hb + (long)rr * Dd + dc) =
                    make_float2(c[rh * 2 + 0], c[rh * 2 + 1]);
            }
        }
    }
}

// ---------------------------------------------------------------------------
extern "C" void kernel_launch(void* const* d_in, const int* in_sizes, int n_in,
                              void* d_out, int out_size) {
    (void)in_sizes; (void)n_in; (void)out_size;
    const float* query = (const float*)d_in[0];
    const float* value = (const float*)d_in[1];
    float* out = (float*)d_out;

    const int SMEM_BYTES = NST * STAGE;   // 96 KB per CTA
    static cudaStream_t s_side = 0;
    static cudaEvent_t ev_fork = 0, ev_join = 0;
    static int init_done = 0;
    if (!init_done) {
        cudaFuncSetAttribute(gemm1_partial, cudaFuncAttributeMaxDynamicSharedMemorySize, SMEM_BYTES);
        cudaFuncSetAttribute(gemm2_out,     cudaFuncAttributeMaxDynamicSharedMemorySize, SMEM_BYTES);
        cudaStreamCreateWithFlags(&s_side, cudaStreamNonBlocking);
        cudaEventCreateWithFlags(&ev_fork, cudaEventDisableTiming);
        cudaEventCreateWithFlags(&ev_join, cudaEventDisableTiming);
        init_done = 1;
    }

    // fork: transpose_v runs on side stream, overlapping rope+gemm1+merge
    cudaEventRecord(ev_fork, 0);
    cudaStreamWaitEvent(s_side, ev_fork, 0);
    dim3 gt(Dd / 32, Tt / 32, Hh);
    transpose_v<<<gt, 256, 0, s_side>>>(value);
    cudaEventRecord(ev_join, s_side);

    rope_kernel<<<32768, 256>>>(query);

    dim3 g1(36, 2, Hh);
    gemm1_partial<<<g1, 128, SMEM_BYTES>>>();

    dim3 gm(288, Hh);
    merge_scores<<<gm, 256>>>();

    // join: gemm2 needs both scores (main) and V^T (side)
    cudaStreamWaitEvent(0, ev_join, 0);
    dim3 g2(Dd / 128, Tt / 128, Hh);
    gemm2_out<<<g2, 128, SMEM_BYTES>>>(out);
}